// round 1
// baseline (speedup 1.0000x reference)
#include <cuda_runtime.h>

#define BB 8
#define HH 512
#define WW 512
#define NN 128
#define HWSZ (HH*WW)
#define TILE 32
#define TPD 16                 // tiles per dim (512/32)
#define NBLK (BB*TPD*TPD)      // 2048 main blocks

// ---- scratch (no allocations allowed) ----
__device__ float g_cy[BB*NN], g_cx[BB*NN], g_inv[BB*NN];
__device__ float g_psm[NBLK], g_phm[NBLK];

// Per-center sigma -> 1/(2*sigma^2), clamped integer centers as floats.
__global__ void k_sigma(const float* __restrict__ sm, const float* __restrict__ gr,
                        const int* __restrict__ centers) {
    int b = blockIdx.x, n = threadIdx.x;
    int cy = centers[(b*NN + n)*2 + 0]; cy = min(max(cy, 0), HH - 1);
    int cx = centers[(b*NN + n)*2 + 1]; cx = min(max(cx, 0), WW - 1);
    float s   = sm[b*HWSZ + cy*WW + cx];
    float grb = gr[b];
    float sigma = 0.2f/grb + fmaxf(s, 0.0f) * 0.2f / grb;   // PR_MIN/gr + relu*RES/gr
    g_cy[b*NN + n]  = (float)cy;
    g_cx[b*NN + n]  = (float)cx;
    g_inv[b*NN + n] = 1.0f / (2.0f * sigma * sigma);
}

// Main fused kernel: one block per 32x32 tile of one sample.
// Computes gt (max-splat via min-q + single exp), hm-loss partial, sm^2 partial.
__global__ void __launch_bounds__(256) k_main(const float* __restrict__ hm,
                                              const float* __restrict__ sm,
                                              const float* __restrict__ mask,
                                              float* __restrict__ out) {
    __shared__ float scy[NN], scx[NN], sinv[NN];
    __shared__ int   scnt;
    __shared__ float red0[8], red1[8];

    int blk = blockIdx.x;
    int b   = blk >> 8;            // 256 tiles per sample
    int t   = blk & 255;
    int y0  = (t >> 4) * TILE;
    int x0  = (t & 15) * TILE;
    int tid = threadIdx.x;

    if (tid == 0) scnt = 0;
    __syncthreads();

    // Cull: keep centers whose minimal q over the tile box is < 104
    // (fp32 exp(-q) == 0 exactly for q > ~103, matching reference underflow).
    if (tid < NN) {
        float cy  = g_cy[b*NN + tid];
        float cx  = g_cx[b*NN + tid];
        float inv = g_inv[b*NN + tid];
        float ddy = fmaxf(fmaxf((float)y0 - cy, cy - (float)(y0 + TILE - 1)), 0.0f);
        float ddx = fmaxf(fmaxf((float)x0 - cx, cx - (float)(x0 + TILE - 1)), 0.0f);
        float qmin = (ddy*ddy + ddx*ddx) * inv;
        if (qmin < 104.0f) {
            int p = atomicAdd(&scnt, 1);   // order irrelevant: fminf is exact & commutative
            scy[p] = cy; scx[p] = cx; sinv[p] = inv;
        }
    }
    __syncthreads();
    int cnt = scnt;

    // Thread layout: 32 columns x 8 row-groups; each thread owns 4 rows (stride 8).
    int x  = x0 + (tid & 31);
    int yb = y0 + (tid >> 5);
    float xf  = (float)x;
    float yf0 = (float)yb, yf1 = (float)(yb + 8), yf2 = (float)(yb + 16), yf3 = (float)(yb + 24);

    float q0 = 1e30f, q1 = 1e30f, q2 = 1e30f, q3 = 1e30f;
    for (int k = 0; k < cnt; k++) {
        float cxk = scx[k], cyk = scy[k], inv = sinv[k];
        float dx = xf - cxk;
        float tq = dx * dx * inv;
        float d0 = yf0 - cyk; q0 = fminf(q0, fmaf(d0*d0, inv, tq));
        float d1 = yf1 - cyk; q1 = fminf(q1, fmaf(d1*d1, inv, tq));
        float d2 = yf2 - cyk; q2 = fminf(q2, fmaf(d2*d2, inv, tq));
        float d3 = yf3 - cyk; q3 = fminf(q3, fmaf(d3*d3, inv, tq));
    }

    float lsm = 0.0f, lhm = 0.0f;
    float* gt_out = out + 2;
    float qv[4] = {q0, q1, q2, q3};
    #pragma unroll
    for (int i = 0; i < 4; i++) {
        int y = yb + 8*i;
        long idx = (long)b * HWSZ + (long)y * WW + x;
        float q = qv[i];
        float g = (q > 103.0f) ? 0.0f : __expf(-q);
        gt_out[idx] = g;
        float h = hm[idx], mk = mask[idx], s = sm[idx];
        float d = h - g;
        lhm = fmaf(d*d, mk, lhm);
        lsm = fmaf(s, s, lsm);
    }

    // Deterministic block reduction (fixed tree order).
    #pragma unroll
    for (int o = 16; o; o >>= 1) {
        lsm += __shfl_down_sync(0xffffffffu, lsm, o);
        lhm += __shfl_down_sync(0xffffffffu, lhm, o);
    }
    int wid = tid >> 5, lane = tid & 31;
    if (lane == 0) { red0[wid] = lsm; red1[wid] = lhm; }
    __syncthreads();
    if (tid == 0) {
        float a = 0.0f, c = 0.0f;
        #pragma unroll
        for (int i = 0; i < 8; i++) { a += red0[i]; c += red1[i]; }
        g_psm[blk] = a;
        g_phm[blk] = c;
    }
}

// Final reduction of 2048 partials -> the two scalar losses.
__global__ void k_final(float* __restrict__ out) {
    __shared__ float ra[8], rc[8];
    int tid = threadIdx.x;
    float a = 0.0f, c = 0.0f;
    for (int i = tid; i < NBLK; i += 256) { a += g_psm[i]; c += g_phm[i]; }
    #pragma unroll
    for (int o = 16; o; o >>= 1) {
        a += __shfl_down_sync(0xffffffffu, a, o);
        c += __shfl_down_sync(0xffffffffu, c, o);
    }
    if ((tid & 31) == 0) { ra[tid >> 5] = a; rc[tid >> 5] = c; }
    __syncthreads();
    if (tid == 0) {
        float sa = 0.0f, sc = 0.0f;
        #pragma unroll
        for (int i = 0; i < 8; i++) { sa += ra[i]; sc += rc[i]; }
        out[0] = sa / (float)((long)BB * HWSZ);   // mean of per-sample mean(sm^2)
        out[1] = sc / (float)((long)BB * HWSZ);   // mean of per-sample masked MSE
    }
}

extern "C" void kernel_launch(void* const* d_in, const int* in_sizes, int n_in,
                              void* d_out, int out_size) {
    const float* hm      = (const float*)d_in[0];
    const float* sm      = (const float*)d_in[1];
    const float* gr      = (const float*)d_in[2];
    const float* mask    = (const float*)d_in[3];
    const int*   centers = (const int*)d_in[4];
    float* out = (float*)d_out;

    k_sigma<<<BB, NN>>>(sm, gr, centers);
    k_main<<<NBLK, 256>>>(hm, sm, mask, out);
    k_final<<<1, 256>>>(out);
}

// round 2
// speedup vs baseline: 1.0194x; 1.0194x over previous
#include <cuda_runtime.h>

#define BB 8
#define HH 512
#define WW 512
#define NN 128
#define HWSZ (HH*WW)
#define TILE 32
#define NBLK (BB*16*16)      // 2048 blocks, one per 32x32 tile

// ---- scratch (no allocations allowed) ----
__device__ float g_psm[NBLK], g_phm[NBLK];
__device__ unsigned int g_done = 0;

// Single fused kernel:
//  - per-block recompute of per-center sigmas (L2-cached gathers)
//  - cull centers vs tile (fp32 exp(-q)==0 exactly for q>~103)
//  - max-splat via min-q + one exp per pixel
//  - fused hm-loss and sm^2 partials
//  - last-block-done final reduction (deterministic fixed-order sum)
__global__ void __launch_bounds__(256) k_fused(const float* __restrict__ hm,
                                               const float* __restrict__ sm,
                                               const float* __restrict__ mask,
                                               const float* __restrict__ gr,
                                               const int*   __restrict__ centers,
                                               float* __restrict__ out) {
    __shared__ float scy[NN], scx[NN], sinv[NN];
    __shared__ int   scnt;
    __shared__ float red0[8], red1[8];
    __shared__ int   s_last;

    int blk = blockIdx.x;
    int b   = blk >> 8;            // 256 tiles per sample
    int t   = blk & 255;
    int y0  = (t >> 4) * TILE;
    int x0  = (t & 15) * TILE;
    int tid = threadIdx.x;

    if (tid == 0) scnt = 0;
    __syncthreads();

    // Per-center sigma + cull, all in one step (threads 0..127).
    if (tid < NN) {
        int cyi = centers[(b*NN + tid)*2 + 0]; cyi = min(max(cyi, 0), HH - 1);
        int cxi = centers[(b*NN + tid)*2 + 1]; cxi = min(max(cxi, 0), WW - 1);
        float s   = __ldg(&sm[b*HWSZ + cyi*WW + cxi]);
        float grb = __ldg(&gr[b]);
        float sigma = 0.2f/grb + fmaxf(s, 0.0f) * 0.2f / grb;  // PR_MIN/gr + relu*RES/gr
        float inv = 1.0f / (2.0f * sigma * sigma);
        float cy = (float)cyi, cx = (float)cxi;
        // min box-distance^2 * inv over this tile
        float ddy = fmaxf(fmaxf((float)y0 - cy, cy - (float)(y0 + TILE - 1)), 0.0f);
        float ddx = fmaxf(fmaxf((float)x0 - cx, cx - (float)(x0 + TILE - 1)), 0.0f);
        float qmin = (ddy*ddy + ddx*ddx) * inv;
        if (qmin < 104.0f) {
            int p = atomicAdd(&scnt, 1);  // order irrelevant: fminf exact & commutative
            scy[p] = cy; scx[p] = cx; sinv[p] = inv;
        }
    }
    __syncthreads();
    int cnt = scnt;

    // Thread layout: 32 columns x 8 row-groups; each thread owns 4 rows (stride 8).
    int x  = x0 + (tid & 31);
    int yb = y0 + (tid >> 5);
    float xf  = (float)x;
    float yf0 = (float)yb, yf1 = (float)(yb + 8), yf2 = (float)(yb + 16), yf3 = (float)(yb + 24);

    float q0 = 1e30f, q1 = 1e30f, q2 = 1e30f, q3 = 1e30f;
    for (int k = 0; k < cnt; k++) {
        float cxk = scx[k], cyk = scy[k], inv = sinv[k];
        float dx = xf - cxk;
        float tq = dx * dx * inv;
        float d0 = yf0 - cyk; q0 = fminf(q0, fmaf(d0*d0, inv, tq));
        float d1 = yf1 - cyk; q1 = fminf(q1, fmaf(d1*d1, inv, tq));
        float d2 = yf2 - cyk; q2 = fminf(q2, fmaf(d2*d2, inv, tq));
        float d3 = yf3 - cyk; q3 = fminf(q3, fmaf(d3*d3, inv, tq));
    }

    float lsm = 0.0f, lhm = 0.0f;
    float* gt_out = out + 2;
    float qv[4] = {q0, q1, q2, q3};
    #pragma unroll
    for (int i = 0; i < 4; i++) {
        int y = yb + 8*i;
        long idx = (long)b * HWSZ + (long)y * WW + x;
        float q = qv[i];
        float g = (q > 103.0f) ? 0.0f : __expf(-q);
        gt_out[idx] = g;
        float h = hm[idx], mk = mask[idx], s = sm[idx];
        float d = h - g;
        lhm = fmaf(d*d, mk, lhm);
        lsm = fmaf(s, s, lsm);
    }

    // Deterministic block reduction (fixed tree order).
    #pragma unroll
    for (int o = 16; o; o >>= 1) {
        lsm += __shfl_down_sync(0xffffffffu, lsm, o);
        lhm += __shfl_down_sync(0xffffffffu, lhm, o);
    }
    int wid = tid >> 5, lane = tid & 31;
    if (lane == 0) { red0[wid] = lsm; red1[wid] = lhm; }
    __syncthreads();
    if (tid == 0) {
        float a = 0.0f, c = 0.0f;
        #pragma unroll
        for (int i = 0; i < 8; i++) { a += red0[i]; c += red1[i]; }
        g_psm[blk] = a;
        g_phm[blk] = c;
        __threadfence();
        unsigned v = atomicAdd(&g_done, 1u);
        s_last = (v == (unsigned)(NBLK - 1)) ? 1 : 0;
    }
    __syncthreads();

    // Last block performs the final reduction (fixed-order, deterministic).
    if (s_last) {
        float a = 0.0f, c = 0.0f;
        for (int i = tid; i < NBLK; i += 256) {
            a += __ldcg(&g_psm[i]);
            c += __ldcg(&g_phm[i]);
        }
        #pragma unroll
        for (int o = 16; o; o >>= 1) {
            a += __shfl_down_sync(0xffffffffu, a, o);
            c += __shfl_down_sync(0xffffffffu, c, o);
        }
        if (lane == 0) { red0[wid] = a; red1[wid] = c; }
        __syncthreads();
        if (tid == 0) {
            float sa = 0.0f, sc = 0.0f;
            #pragma unroll
            for (int i = 0; i < 8; i++) { sa += red0[i]; sc += red1[i]; }
            out[0] = sa / (float)((long)BB * HWSZ);   // mean of per-sample mean(sm^2)
            out[1] = sc / (float)((long)BB * HWSZ);   // mean of per-sample masked MSE
            g_done = 0;   // reset for next graph replay (deterministic)
        }
    }
}

extern "C" void kernel_launch(void* const* d_in, const int* in_sizes, int n_in,
                              void* d_out, int out_size) {
    const float* hm      = (const float*)d_in[0];
    const float* sm      = (const float*)d_in[1];
    const float* gr      = (const float*)d_in[2];
    const float* mask    = (const float*)d_in[3];
    const int*   centers = (const int*)d_in[4];
    float* out = (float*)d_out;

    k_fused<<<NBLK, 256>>>(hm, sm, mask, gr, centers, out);
}

// round 4
// speedup vs baseline: 1.1771x; 1.1546x over previous
#include <cuda_runtime.h>

#define BB 8
#define HH 512
#define WW 512
#define NN 128
#define HWSZ (HH*WW)
#define TILE 64
#define TPD  8                 // tiles per dim (512/64)
#define NBLK (BB*TPD*TPD)      // 512 blocks

// ---- scratch (no allocations allowed) ----
__device__ float g_psm[NBLK], g_phm[NBLK];
__device__ unsigned int g_done = 0;

// One block per 64x64 tile. 256 threads; each thread owns a 4-wide x-group
// across 4 rows (stride 16) = 16 pixels. float4 loads; float2 gt stores
// (gt base = out+2 is only 8-byte aligned).
__global__ void __launch_bounds__(256, 4) k_fused(const float* __restrict__ hm,
                                                  const float* __restrict__ sm,
                                                  const float* __restrict__ mask,
                                                  const float* __restrict__ gr,
                                                  const int*   __restrict__ centers,
                                                  float* __restrict__ out) {
    __shared__ float scy[NN], scx[NN], sinv[NN];
    __shared__ int   scnt;
    __shared__ float red0[8], red1[8];
    __shared__ int   s_last;

    int blk = blockIdx.x;
    int b   = blk >> 6;            // 64 tiles per sample
    int t   = blk & 63;
    int y0  = (t >> 3) * TILE;
    int x0  = (t & 7)  * TILE;
    int tid = threadIdx.x;
    int tx  = tid & 15;            // x-group (4 px each)
    int ty  = tid >> 4;            // row within group of 16

    if (tid == 0) scnt = 0;
    __syncthreads();

    int x = x0 + tx * 4;
    // element index of first pixel in each of the 4 rows (y = y0+ty+16r)
    long e0 = (long)b * HWSZ + (long)(y0 + ty) * WW + x;
    long e1 = e0 + 16L * WW;
    long e2 = e1 + 16L * WW;
    long e3 = e2 + 16L * WW;

    const float4* sm4 = (const float4*)sm;
    const float4* hm4 = (const float4*)hm;
    const float4* mk4 = (const float4*)mask;
    float* gt = out + 2;

    // Prefetch sm rows (independent of centers) — overlaps sigma gather latency.
    float4 s0 = sm4[e0 >> 2], s1 = sm4[e1 >> 2], s2 = sm4[e2 >> 2], s3 = sm4[e3 >> 2];

    // Per-center sigma + cull (threads 0..127): fp32 exp(-q)==0 exactly for q>~103.
    if (tid < NN) {
        int cyi = centers[(b*NN + tid)*2 + 0]; cyi = min(max(cyi, 0), HH - 1);
        int cxi = centers[(b*NN + tid)*2 + 1]; cxi = min(max(cxi, 0), WW - 1);
        float s   = __ldg(&sm[b*HWSZ + cyi*WW + cxi]);
        float grb = __ldg(&gr[b]);
        float sigma = 0.2f/grb + fmaxf(s, 0.0f) * 0.2f / grb;  // PR_MIN/gr + relu*RES/gr
        float inv = 1.0f / (2.0f * sigma * sigma);
        float cy = (float)cyi, cx = (float)cxi;
        float ddy = fmaxf(fmaxf((float)y0 - cy, cy - (float)(y0 + TILE - 1)), 0.0f);
        float ddx = fmaxf(fmaxf((float)x0 - cx, cx - (float)(x0 + TILE - 1)), 0.0f);
        float qmin = (ddy*ddy + ddx*ddx) * inv;
        if (qmin < 104.0f) {
            int p = atomicAdd(&scnt, 1);  // order irrelevant: fminf exact & commutative
            scy[p] = cy; scx[p] = cx; sinv[p] = inv;
        }
    }

    // sm^2 partial while the gather chain drains.
    float lsm = 0.0f;
    lsm = fmaf(s0.x,s0.x, fmaf(s0.y,s0.y, fmaf(s0.z,s0.z, fmaf(s0.w,s0.w, lsm))));
    lsm = fmaf(s1.x,s1.x, fmaf(s1.y,s1.y, fmaf(s1.z,s1.z, fmaf(s1.w,s1.w, lsm))));
    lsm = fmaf(s2.x,s2.x, fmaf(s2.y,s2.y, fmaf(s2.z,s2.z, fmaf(s2.w,s2.w, lsm))));
    lsm = fmaf(s3.x,s3.x, fmaf(s3.y,s3.y, fmaf(s3.z,s3.z, fmaf(s3.w,s3.w, lsm))));

    __syncthreads();
    int cnt = scnt;

    float xf = (float)x;
    float yf[4];
    yf[0] = (float)(y0 + ty); yf[1] = yf[0] + 16.0f;
    yf[2] = yf[0] + 32.0f;    yf[3] = yf[0] + 48.0f;

    float q[4][4];
    #pragma unroll
    for (int r = 0; r < 4; r++)
        #pragma unroll
        for (int j = 0; j < 4; j++) q[r][j] = 1e30f;

    for (int k = 0; k < cnt; k++) {
        float cxk = scx[k], cyk = scy[k], inv = sinv[k];
        float ax[4];
        #pragma unroll
        for (int j = 0; j < 4; j++) {
            float dx = xf + (float)j - cxk;
            ax[j] = dx * dx * inv;
        }
        #pragma unroll
        for (int r = 0; r < 4; r++) {
            float dy = yf[r] - cyk;
            float by = dy * dy * inv;
            #pragma unroll
            for (int j = 0; j < 4; j++)
                q[r][j] = fminf(q[r][j], ax[j] + by);
        }
    }

    // gt + losses, row by row (float4 loads, float2 gt stores).
    float lhm = 0.0f;
    long er[4] = {e0, e1, e2, e3};
    #pragma unroll
    for (int r = 0; r < 4; r++) {
        float g0 = (q[r][0] > 103.0f) ? 0.0f : __expf(-q[r][0]);
        float g1 = (q[r][1] > 103.0f) ? 0.0f : __expf(-q[r][1]);
        float g2 = (q[r][2] > 103.0f) ? 0.0f : __expf(-q[r][2]);
        float g3 = (q[r][3] > 103.0f) ? 0.0f : __expf(-q[r][3]);
        float4 h  = hm4[er[r] >> 2];
        float4 mk = mk4[er[r] >> 2];
        *(float2*)(gt + er[r])     = make_float2(g0, g1);
        *(float2*)(gt + er[r] + 2) = make_float2(g2, g3);
        float d0 = h.x - g0, d1 = h.y - g1, d2 = h.z - g2, d3 = h.w - g3;
        lhm = fmaf(d0*d0, mk.x, lhm);
        lhm = fmaf(d1*d1, mk.y, lhm);
        lhm = fmaf(d2*d2, mk.z, lhm);
        lhm = fmaf(d3*d3, mk.w, lhm);
    }

    // Deterministic block reduction (fixed tree order).
    #pragma unroll
    for (int o = 16; o; o >>= 1) {
        lsm += __shfl_down_sync(0xffffffffu, lsm, o);
        lhm += __shfl_down_sync(0xffffffffu, lhm, o);
    }
    int wid = tid >> 5, lane = tid & 31;
    if (lane == 0) { red0[wid] = lsm; red1[wid] = lhm; }
    __syncthreads();
    if (tid == 0) {
        float a = 0.0f, c = 0.0f;
        #pragma unroll
        for (int i = 0; i < 8; i++) { a += red0[i]; c += red1[i]; }
        g_psm[blk] = a;
        g_phm[blk] = c;
        __threadfence();
        unsigned v = atomicAdd(&g_done, 1u);
        s_last = (v == (unsigned)(NBLK - 1)) ? 1 : 0;
    }
    __syncthreads();

    // Last block: final reduction (fixed order, deterministic).
    if (s_last) {
        float a = 0.0f, c = 0.0f;
        for (int i = tid; i < NBLK; i += 256) {
            a += __ldcg(&g_psm[i]);
            c += __ldcg(&g_phm[i]);
        }
        #pragma unroll
        for (int o = 16; o; o >>= 1) {
            a += __shfl_down_sync(0xffffffffu, a, o);
            c += __shfl_down_sync(0xffffffffu, c, o);
        }
        if (lane == 0) { red0[wid] = a; red1[wid] = c; }
        __syncthreads();
        if (tid == 0) {
            float sa = 0.0f, sc = 0.0f;
            #pragma unroll
            for (int i = 0; i < 8; i++) { sa += red0[i]; sc += red1[i]; }
            out[0] = sa / (float)((long)BB * HWSZ);   // mean of per-sample mean(sm^2)
            out[1] = sc / (float)((long)BB * HWSZ);   // mean of per-sample masked MSE
            g_done = 0;   // reset for next graph replay
        }
    }
}

extern "C" void kernel_launch(void* const* d_in, const int* in_sizes, int n_in,
                              void* d_out, int out_size) {
    const float* hm      = (const float*)d_in[0];
    const float* sm      = (const float*)d_in[1];
    const float* gr      = (const float*)d_in[2];
    const float* mask    = (const float*)d_in[3];
    const int*   centers = (const int*)d_in[4];
    float* out = (float*)d_out;

    k_fused<<<NBLK, 256>>>(hm, sm, mask, gr, centers, out);
}